// round 2
// baseline (speedup 1.0000x reference)
#include <cuda_runtime.h>
#include <math.h>

#define MAXB   (1 << 17)
#define MAXBLK 4096

__device__ __align__(16) float g_Acoef[81 * 4];     // [m][ow]
__device__ __align__(16) float g_pooled[MAXB * 4];  // angles per item
__device__ __align__(16) float g_q[MAXB * 4];       // q per item
__device__ __align__(16) float g_part[MAXBLK * 8];  // per-block partial sums
__device__ __align__(16) float g_norm[8];           // scale[4], bias[4]

struct C2 { float re, im; };

// ---------------------------------------------------------------------------
// Setup: build the 4x81 multilinear coefficient table from weights (on device,
// every launch -> deterministic + graph-capturable).
// ---------------------------------------------------------------------------
__global__ void setup_kernel(const float* __restrict__ W)  // [2][4][3]
{
    __shared__ C2 M[16][16];        // M[i][j]: circuit matrix (post-initial-RX part)
    __shared__ float G[4][16][16];  // real quadratic forms
    int tid = threadIdx.x;

    if (tid < 16) {
        int j = tid;
        C2 st[16];
#pragma unroll
        for (int i = 0; i < 16; i++) { st[i].re = (i == j) ? 1.f : 0.f; st[i].im = 0.f; }

#pragma unroll
        for (int l = 0; l < 2; l++) {
#pragma unroll
            for (int w = 0; w < 4; w++) {
                float ax = W[(l * 4 + w) * 3 + 0] * 0.5f;
                float ay = W[(l * 4 + w) * 3 + 1] * 0.5f;
                float az = W[(l * 4 + w) * 3 + 2] * 0.5f;
                const int mask = 1 << (3 - w);
                // RX: [[c, -is], [-is, c]]
                {
                    float c = cosf(ax), s = sinf(ax);
#pragma unroll
                    for (int i = 0; i < 16; i++) {
                        if (i & mask) continue;
                        C2 a = st[i], b = st[i | mask];
                        st[i]        = { c * a.re + s * b.im,  c * a.im - s * b.re };
                        st[i | mask] = { s * a.im + c * b.re, -s * a.re + c * b.im };
                    }
                }
                // RY: [[c, -s], [s, c]]
                {
                    float c = cosf(ay), s = sinf(ay);
#pragma unroll
                    for (int i = 0; i < 16; i++) {
                        if (i & mask) continue;
                        C2 a = st[i], b = st[i | mask];
                        st[i]        = { c * a.re - s * b.re, c * a.im - s * b.im };
                        st[i | mask] = { s * a.re + c * b.re, s * a.im + c * b.im };
                    }
                }
                // RZ: diag(e^-iaz, e^+iaz)
                {
                    float c = cosf(az), s = sinf(az);
#pragma unroll
                    for (int i = 0; i < 16; i++) {
                        C2 a = st[i];
                        if (i & mask) st[i] = { c * a.re - s * a.im, c * a.im + s * a.re };
                        else          st[i] = { c * a.re + s * a.im, c * a.im - s * a.re };
                    }
                }
            }
            // CNOT ring: new[i] = old[perm[i]], perm[i] = (bit(i,c)? i^tm : i)
#pragma unroll
            for (int w = 0; w < 4; w++) {
                int t = (w + 1) & 3;
                int cm = 1 << (3 - w), tm = 1 << (3 - t);
                C2 tmp[16];
#pragma unroll
                for (int i = 0; i < 16; i++) tmp[i] = st[(i & cm) ? (i ^ tm) : i];
#pragma unroll
                for (int i = 0; i < 16; i++) st[i] = tmp[i];
            }
        }
#pragma unroll
        for (int i = 0; i < 16; i++) M[i][j] = st[i];
    }
    __syncthreads();

    // Stage 2: G_ow[j][k] = Re( i^(pc(j)-pc(k)) * sum_i sign_ow(i) conj(M[i][j]) M[i][k] )
    {
        int ow = tid >> 8;
        int j = (tid >> 4) & 15;
        int k = tid & 15;
        float hr = 0.f, hi = 0.f;
#pragma unroll
        for (int i = 0; i < 16; i++) {
            float sgn = ((i >> (3 - ow)) & 1) ? -1.f : 1.f;
            C2 a = M[i][j], b = M[i][k];
            hr += sgn * (a.re * b.re + a.im * b.im);
            hi += sgn * (a.re * b.im - a.im * b.re);
        }
        int ph = (__popc(j) - __popc(k)) & 3;
        float g = (ph == 0) ? hr : (ph == 1) ? -hi : (ph == 2) ? -hr : hi;
        G[ow][j][k] = g;
    }
    __syncthreads();

    // Stage 3: multilinear coefficients A_ow[m], m in base-3 over 4 wires
    if (tid < 324) {
        int ow = tid / 81;
        int m = tid % 81;
        int md0 = m / 27, md1 = (m / 9) % 3, md2 = (m / 3) % 3, md3 = m % 3;
        int md[4] = { md0, md1, md2, md3 };
        float acc = 0.f;
#pragma unroll
        for (int t = 0; t < 16; t++) {
            int j = 0, k = 0;
            float sgn = 1.f;
#pragma unroll
            for (int w = 0; w < 4; w++) {
                int tb = (t >> (3 - w)) & 1;
                int jb, kb;
                if (md[w] == 2) { jb = tb; kb = 1 - tb; }
                else { jb = tb; kb = tb; if (md[w] == 1 && tb == 1) sgn = -sgn; }
                j |= jb << (3 - w);
                k |= kb << (3 - w);
            }
            acc += sgn * G[ow][j][k];
        }
        g_Acoef[m * 4 + ow] = acc * (1.f / 16.f);
    }
}

// ---------------------------------------------------------------------------
// Pooling: warp-per-item, fully coalesced 512B loads, butterfly reduce,
// coalesced float4 angle store.
// ---------------------------------------------------------------------------
__global__ void pool_kernel(const float* __restrict__ x, int B)
{
    int gw = (blockIdx.x * blockDim.x + threadIdx.x) >> 5;
    int lane = threadIdx.x & 31;
    int base = gw * 32;
    if (base >= B) return;

    // Per-lane constant wire classification.
    int p0 = lane * 4;
    int rb0 = (p0 >= 72) ? 2 : 0;   // rows >= 6 -> wires {2,3}
    int off0 = p0 % 12;             // in {0,4,8}; each float4 stays in one row
    int wA0 = rb0 + (off0 == 8);    // cols (off,off+1)
    int wB0 = rb0 + (off0 >= 4);    // cols (off+2,off+3)
    int p1 = 128 + lane * 4;        // second float4, lanes 0..3 only (rows 10,11)
    int off1 = p1 % 12;
    int wA1 = (lane < 4) ? (2 + (off1 == 8)) : -1;
    int wB1 = (lane < 4) ? (2 + (off1 >= 4)) : -1;

    float mA00 = (wA0 == 0), mA01 = (wA0 == 1), mA02 = (wA0 == 2), mA03 = (wA0 == 3);
    float mB00 = (wB0 == 0), mB01 = (wB0 == 1), mB02 = (wB0 == 2), mB03 = (wB0 == 3);
    float mA12 = (wA1 == 2), mA13 = (wA1 == 3);
    float mB12 = (wB1 == 2), mB13 = (wB1 == 3);

    float4 keep = make_float4(0.f, 0.f, 0.f, 0.f);
    const float4* xb = (const float4*)x;

#pragma unroll 4
    for (int it = 0; it < 32; it++) {
        int item = base + it;
        if (item >= B) break;
        const float4* p = xb + (size_t)item * 36;
        float4 v0 = p[lane];
        float4 v1 = make_float4(0.f, 0.f, 0.f, 0.f);
        if (lane < 4) v1 = p[32 + lane];

        float sA0 = v0.x + v0.y, sB0 = v0.z + v0.w;
        float sA1 = v1.x + v1.y, sB1 = v1.z + v1.w;

        float a0 = mA00 * sA0 + mB00 * sB0;
        float a1 = mA01 * sA0 + mB01 * sB0;
        float a2 = mA02 * sA0 + mB02 * sB0 + mA12 * sA1 + mB12 * sB1;
        float a3 = mA03 * sA0 + mB03 * sB0 + mA13 * sA1 + mB13 * sB1;

#pragma unroll
        for (int s = 16; s; s >>= 1) {
            a0 += __shfl_xor_sync(0xffffffffu, a0, s);
            a1 += __shfl_xor_sync(0xffffffffu, a1, s);
            a2 += __shfl_xor_sync(0xffffffffu, a2, s);
            a3 += __shfl_xor_sync(0xffffffffu, a3, s);
        }
        keep.x = (lane == it) ? a0 : keep.x;
        keep.y = (lane == it) ? a1 : keep.y;
        keep.z = (lane == it) ? a2 : keep.z;
        keep.w = (lane == it) ? a3 : keep.w;
    }

    const float inv = 1.f / 36.f;
    keep.x *= inv; keep.y *= inv; keep.z *= inv; keep.w *= inv;
    if (base + lane < B)
        ((float4*)g_pooled)[base + lane] = keep;   // coalesced
}

// ---------------------------------------------------------------------------
// Circuit evaluation (thread-per-item) + per-block sum / sumsq partials.
// ---------------------------------------------------------------------------
__global__ void circuit_kernel(int B)
{
    __shared__ float4 As[81];
    __shared__ float wsum[8][8];
    int tid = threadIdx.x;
    if (tid < 81) As[tid] = ((const float4*)g_Acoef)[tid];
    __syncthreads();

    int item = blockIdx.x * 256 + tid;
    float q0 = 0.f, q1 = 0.f, q2 = 0.f, q3 = 0.f;
    if (item < B) {
        float4 ang = ((const float4*)g_pooled)[item];
        float c0, s0, c1, s1, c2, s2, c3, s3;
        __sincosf(ang.x, &s0, &c0);
        __sincosf(ang.y, &s1, &c1);
        __sincosf(ang.z, &s2, &c2);
        __sincosf(ang.w, &s3, &c3);

        float t01[9] = { 1.f, c1, s1, c0, c0 * c1, c0 * s1, s0, s0 * c1, s0 * s1 };
        float t23[9] = { 1.f, c3, s3, c2, c2 * c3, c2 * s3, s2, s2 * c3, s2 * s3 };

#pragma unroll
        for (int m = 0; m < 81; m++) {
            float bs = t01[m / 9] * t23[m % 9];
            float4 a = As[m];
            q0 = fmaf(a.x, bs, q0);
            q1 = fmaf(a.y, bs, q1);
            q2 = fmaf(a.z, bs, q2);
            q3 = fmaf(a.w, bs, q3);
        }
        ((float4*)g_q)[item] = make_float4(q0, q1, q2, q3);
    }

    float v[8] = { q0, q1, q2, q3, q0 * q0, q1 * q1, q2 * q2, q3 * q3 };
#pragma unroll
    for (int s = 16; s; s >>= 1)
#pragma unroll
        for (int k = 0; k < 8; k++) v[k] += __shfl_xor_sync(0xffffffffu, v[k], s);

    int w = tid >> 5, lane = tid & 31;
    if (lane == 0) {
#pragma unroll
        for (int k = 0; k < 8; k++) wsum[w][k] = v[k];
    }
    __syncthreads();
    if (tid < 8) {
        float acc = 0.f;
#pragma unroll
        for (int ww = 0; ww < 8; ww++) acc += wsum[ww][tid];
        g_part[blockIdx.x * 8 + tid] = acc;
    }
}

// ---------------------------------------------------------------------------
// Finalize: deterministic double-precision reduction of block partials.
// ---------------------------------------------------------------------------
__global__ void finalize_kernel(const float* __restrict__ gamma,
                                const float* __restrict__ beta,
                                int B, int nblocks)
{
    __shared__ double wacc[8][8];
    __shared__ double tot[8];
    int tid = threadIdx.x;
    double acc[8] = { 0, 0, 0, 0, 0, 0, 0, 0 };
    for (int b = tid; b < nblocks; b += blockDim.x) {
#pragma unroll
        for (int k = 0; k < 8; k++) acc[k] += (double)g_part[b * 8 + k];
    }
#pragma unroll
    for (int s = 16; s; s >>= 1)
#pragma unroll
        for (int k = 0; k < 8; k++) acc[k] += __shfl_xor_sync(0xffffffffu, acc[k], s);

    int w = tid >> 5;
    if ((tid & 31) == 0) {
#pragma unroll
        for (int k = 0; k < 8; k++) wacc[w][k] = acc[k];
    }
    __syncthreads();
    if (tid < 8) {
        double t = 0;
#pragma unroll
        for (int ww = 0; ww < 8; ww++) t += wacc[ww][tid];
        tot[tid] = t;
    }
    __syncthreads();
    if (tid < 4) {
        double mean = tot[tid] / (double)B;
        double var = tot[4 + tid] / (double)B - mean * mean;
        float scale = gamma[tid] * rsqrtf((float)var + 1e-5f);
        g_norm[tid] = scale;
        g_norm[4 + tid] = beta[tid] - (float)mean * scale;
    }
}

// ---------------------------------------------------------------------------
// Normalize: out = q * scale + bias  (q is L2-hot)
// ---------------------------------------------------------------------------
__global__ void norm_kernel(float* __restrict__ out, int B)
{
    int item = blockIdx.x * blockDim.x + threadIdx.x;
    if (item >= B) return;
    float4 q = ((const float4*)g_q)[item];
    float4 sc = *(const float4*)&g_norm[0];
    float4 bs = *(const float4*)&g_norm[4];
    float4 o;
    o.x = fmaf(q.x, sc.x, bs.x);
    o.y = fmaf(q.y, sc.y, bs.y);
    o.z = fmaf(q.z, sc.z, bs.z);
    o.w = fmaf(q.w, sc.w, bs.w);
    ((float4*)out)[item] = o;
}

// ---------------------------------------------------------------------------
extern "C" void kernel_launch(void* const* d_in, const int* in_sizes, int n_in,
                              void* d_out, int out_size)
{
    const float* x     = (const float*)d_in[0];
    const float* W     = (const float*)d_in[1];
    const float* gamma = (const float*)d_in[2];
    const float* beta  = (const float*)d_in[3];
    float* out = (float*)d_out;

    int B = in_sizes[0] / 144;

    setup_kernel<<<1, 1024>>>(W);

    int warpsTotal = (B + 31) / 32;
    int poolBlocks = (warpsTotal + 7) / 8;
    pool_kernel<<<poolBlocks, 256>>>(x, B);

    int cblocks = (B + 255) / 256;
    circuit_kernel<<<cblocks, 256>>>(B);

    finalize_kernel<<<1, 256>>>(gamma, beta, B, cblocks);

    norm_kernel<<<cblocks, 256>>>(out, B);
}